// round 8
// baseline (speedup 1.0000x reference)
#include <cuda_runtime.h>
#include <cuda_fp16.h>
#include <math.h>
#include <stdint.h>

#define BATCH 16
#define NP    10000
#define NNB   10
#define NCOL  48
#define BPAD  10016          // padded K for B operand (multiple of 32)
#define BK    32
#define NKT   313            // ceil(10000/32)
#define MT    128
#define NMT   79             // ceil(10000/128)
#define TILES_TOTAL (NMT * NKT)   // 24727
#define NCTA  444            // 148 SMs x 3 CTAs
#define WBASE (TILES_TOTAL / NCTA)        // 55
#define WREM  (TILES_TOTAL - WBASE * NCTA) // 307

#define TPAD  12             // padded T row (floats) -> float4 aligned

// GEMM smem geometry (bytes)
#define AROW  40                       // A row stride in fp32 elems (160 B)
#define BROW  40                       // B row stride in fp16 elems (80 B)
#define A_BYTES (128 * AROW * 4)       // 20480
#define B_BYTES (NCOL * BROW * 2)      // 3840
#define STAGE_BYTES (A_BYTES + B_BYTES)  // 24320
#define NSTAGE 3
#define DSMEM (NSTAGE * STAGE_BYTES)   // 72960

// ---------------- scratch (__device__ globals; zero-init) ------------------
__device__ __align__(16) float g_T[NP * BATCH * TPAD];  // [p][b][12]
__device__ __align__(16) __half g_bh[NCOL * BPAD];      // B fp16 [c][k]

__device__ __forceinline__ uint32_t smem_u32(const void* p) {
    uint32_t a;
    asm("{ .reg .u64 t; cvta.to.shared.u64 t, %1; cvt.u32.u64 %0, t; }"
        : "=r"(a) : "l"(p));
    return a;
}

#define LDSM4(r0, r1, r2, r3, addr) \
    asm volatile("ldmatrix.sync.aligned.m8n8.x4.shared.b16 {%0,%1,%2,%3}, [%4];" \
                 : "=r"(r0), "=r"(r1), "=r"(r2), "=r"(r3) : "r"(addr))

#define MMA(d, a0, a1, a2, a3, b0, b1) \
    asm volatile("mma.sync.aligned.m16n8k16.row.col.f32.f16.f16.f32 " \
                 "{%0,%1,%2,%3}, {%4,%5,%6,%7}, {%8,%9}, {%0,%1,%2,%3};" \
                 : "+f"((d)[0]), "+f"((d)[1]), "+f"((d)[2]), "+f"((d)[3]) \
                 : "r"(a0), "r"(a1), "r"(a2), "r"(a3), "r"(b0), "r"(b1))

#define CVT_H2(d, hi, lo) \
    asm("cvt.rn.f16x2.f32 %0, %1, %2;" : "=r"(d) : "f"(hi), "f"(lo))

#define CPA16(dst, src, sz) \
    asm volatile("cp.async.cg.shared.global [%0], [%1], 16, %2;" \
                 :: "r"(dst), "l"(src), "r"(sz) : "memory")
#define CPA_COMMIT() asm volatile("cp.async.commit_group;" ::: "memory")

// ---------------------------------------------------------------------------
// Kernel 1: T[b,p] = R(f[:3]) @ S(f[3:9]); store padded [p][b][12].
// Staged float4 reads + float4 writes. Zeroes output buffer.
// ---------------------------------------------------------------------------
__global__ __launch_bounds__(256) void ftoT_kernel(const float* __restrict__ geo,
                                                   float4* __restrict__ outz) {
    __shared__ float sg[16 * 152];   // staged geo: [b][144 +8 pad]
    __shared__ float sT[16 * 200];   // staged out: [pi][192 +8 pad]

    const int tid = threadIdx.x;
    const int bb = tid >> 4;
    const int pi = tid & 15;
    const int p0 = blockIdx.x * 16;

    {   // zero output: 120000 float4 total
        int gz = blockIdx.x * 256 + tid;
        if (gz < 120000)
            outz[gz] = make_float4(0.f, 0.f, 0.f, 0.f);
    }

    // stage geo: 16 chunks (one per b) of 36 float4 (144 floats = 16 p x 9)
#pragma unroll
    for (int q = tid; q < 576; q += 256) {
        int b = q / 36, i = q - b * 36;
        float4 v = __ldg(reinterpret_cast<const float4*>(
                             geo + ((size_t)b * NP + p0) * 9) + i);
        *reinterpret_cast<float4*>(&sg[b * 152 + i * 4]) = v;
    }
    __syncthreads();

    const float* f = &sg[bb * 152 + pi * 9];
    float x = f[0], y = f[1], z = f[2];
    float s3 = f[3], s4 = f[4], s5 = f[5], s6 = f[6], s7 = f[7], s8 = f[8];

    float th = sqrtf(x * x + y * y + z * z);
    float R00, R01, R02, R10, R11, R12, R20, R21, R22;
    if (th == 0.0f) {
        R00 = 1.f; R01 = 0.f; R02 = 0.f;
        R10 = 0.f; R11 = 1.f; R12 = 0.f;
        R20 = 0.f; R21 = 0.f; R22 = 1.f;
    } else {
        float inv = 1.0f / th;
        float ka = x * inv, kb = y * inv, kc = z * inv;
        float st, ct;
        __sincosf(th, &st, &ct);
        float omc = 1.0f - ct;
        R00 = 1.0f - omc * (ka * ka + kb * kb);
        R01 =  st * ka - omc * kb * kc;
        R02 =  st * kb + omc * ka * kc;
        R10 = -st * ka - omc * kb * kc;
        R11 = 1.0f - omc * (ka * ka + kc * kc);
        R12 =  st * kc - omc * ka * kb;
        R20 = -st * kb + omc * ka * kc;
        R21 = -st * kc - omc * ka * kb;
        R22 = 1.0f - omc * (kb * kb + kc * kc);
    }
    float* o = &sT[pi * 200 + bb * TPAD];
    o[0] = R00 * s3 + R01 * s4 + R02 * s5;
    o[1] = R00 * s4 + R01 * s6 + R02 * s7;
    o[2] = R00 * s5 + R01 * s7 + R02 * s8;
    o[3] = R10 * s3 + R11 * s4 + R12 * s5;
    o[4] = R10 * s4 + R11 * s6 + R12 * s7;
    o[5] = R10 * s5 + R11 * s7 + R12 * s8;
    o[6] = R20 * s3 + R21 * s4 + R22 * s5;
    o[7] = R20 * s4 + R21 * s6 + R22 * s7;
    o[8] = R20 * s5 + R21 * s7 + R22 * s8;
    o[9] = 0.f; o[10] = 0.f; o[11] = 0.f;
    __syncthreads();

    // write out: 16 p x 48 float4 contiguous
    float4* dst = reinterpret_cast<float4*>(g_T + (size_t)p0 * (BATCH * TPAD));
#pragma unroll
    for (int q = tid; q < 768; q += 256) {
        int pr = q / 48, col = q - pr * 48;
        dst[q] = *reinterpret_cast<const float4*>(&sT[pr * 200 + col * 4]);
    }
}

// ---------------------------------------------------------------------------
// Kernel 2: bvec -> transposed fp16 g_bh[c][k]; vectorized float4 T gathers.
// ---------------------------------------------------------------------------
__global__ void bvec_kernel(const int* __restrict__ nb,
                            const float* __restrict__ vdiff) {
    int t = blockIdx.x * blockDim.x + threadIdx.x;
    int bb = t & (BATCH - 1);
    int p  = t >> 4;
    if (p >= NP) return;

    const float4* Tp = reinterpret_cast<const float4*>(
        g_T + ((size_t)p * BATCH + bb) * TPAD);
    float4 t0 = __ldg(Tp), t1 = __ldg(Tp + 1), t2 = __ldg(Tp + 2);

    float a0 = 0.f, a1 = 0.f, a2 = 0.f;
    float v0s = 0.f, v1s = 0.f, v2s = 0.f;

#pragma unroll
    for (int n = 0; n < NNB; n++) {
        int idx = __ldg(nb + p * NNB + n);
        const float* vd = vdiff + ((size_t)p * NNB + n) * 3;
        float v0 = __ldg(vd + 0), v1 = __ldg(vd + 1), v2 = __ldg(vd + 2);
        v0s += v0; v1s += v1; v2s += v2;
        if (idx > 0) {
            const float4* Tn = reinterpret_cast<const float4*>(
                g_T + ((size_t)(idx - 1) * BATCH + bb) * TPAD);
            float4 n0 = __ldg(Tn), n1 = __ldg(Tn + 1), n2 = __ldg(Tn + 2);
            a0 += n0.x * v0 + n0.y * v1 + n0.z * v2;
            a1 += n0.w * v0 + n1.x * v1 + n1.y * v2;
            a2 += n1.z * v0 + n1.w * v1 + n2.x * v2;
        }
    }
    a0 += t0.x * v0s + t0.y * v1s + t0.z * v2s;
    a1 += t0.w * v0s + t1.x * v1s + t1.y * v2s;
    a2 += t1.z * v0s + t1.w * v1s + t2.x * v2s;

    int c = bb * 3;
    g_bh[(size_t)(c + 0) * BPAD + p] = __float2half_rn(a0);
    g_bh[(size_t)(c + 1) * BPAD + p] = __float2half_rn(a1);
    g_bh[(size_t)(c + 2) * BPAD + p] = __float2half_rn(a2);
}

// ---------------------------------------------------------------------------
// Kernel 3: stream-K fp16 GEMM (unchanged from R7).
// ---------------------------------------------------------------------------
__global__ __launch_bounds__(256, 3) void gemm_mma(const float* __restrict__ A,
                                                   float* __restrict__ out) {
    extern __shared__ __align__(16) char dsm[];

    const int t = threadIdx.x;
    const int w = t >> 5;
    const int l = t & 31;

    const int g   = l >> 2;
    const int tig = l & 3;
    const int mat = l >> 3, mrow = l & 7;

    const uint32_t smb = smem_u32(dsm);
    const int b_off = (((mat >> 1) << 3) + mrow) * BROW + ((mat & 1) << 3);

    const bool bldr = (t < 192);
    const int br = t >> 2, bseg = t & 3;

    const int ct = blockIdx.x;
    int start = ct * WBASE + (ct < WREM ? ct : WREM);
    int remn  = WBASE + (ct < WREM ? 1 : 0);

    while (remn > 0) {
        const int m   = start / NKT;
        const int kti = start - m * NKT;
        int seg = NKT - kti; if (seg > remn) seg = remn;
        const int row0 = m * MT;

        float acc[6][4];
#pragma unroll
        for (int i = 0; i < 6; i++)
#pragma unroll
            for (int j = 0; j < 4; j++) acc[i][j] = 0.f;

        auto issue_tile = [&](int i) {
            int k0 = (kti + i) * BK;
            int st = i % NSTAGE;
            uint32_t abase = smb + st * STAGE_BYTES;
            uint32_t bbase = abase + A_BYTES;
#pragma unroll
            for (int j = 0; j < 4; j++) {
                int q = j * 256 + t;
                int r = q >> 3, c = q & 7;
                int grow = row0 + r, gk = k0 + c * 4;
                uint32_t sz = (grow < NP && gk < NP) ? 16u : 0u;
                CPA16(abase + (uint32_t)(r * AROW + c * 4) * 4,
                      A + (size_t)grow * NP + gk, sz);
            }
            if (bldr) {
                CPA16(bbase + (uint32_t)(br * BROW + bseg * 8) * 2,
                      g_bh + (size_t)br * BPAD + k0 + bseg * 8, 16u);
            }
            CPA_COMMIT();
        };

        issue_tile(0);
        if (seg > 1) issue_tile(1);
        else CPA_COMMIT();

        for (int i = 0; i < seg; i++) {
            if (i + 1 < seg) {
                asm volatile("cp.async.wait_group 1;" ::: "memory");
            } else {
                asm volatile("cp.async.wait_group 0;" ::: "memory");
            }
            __syncthreads();
            if (i + 2 < seg) issue_tile(i + 2);

            int st = i % NSTAGE;
            const float* smA = reinterpret_cast<const float*>(dsm + st * STAGE_BYTES);
            uint32_t bb2 = smb + st * STAGE_BYTES + A_BYTES;

#pragma unroll
            for (int ks = 0; ks < 2; ks++) {
                const int c0 = ks * 16 + tig * 2;
                const float2 v0 = *reinterpret_cast<const float2*>(&smA[(w * 16 + g) * AROW + c0]);
                const float2 v1 = *reinterpret_cast<const float2*>(&smA[(w * 16 + g + 8) * AROW + c0]);
                const float2 v2 = *reinterpret_cast<const float2*>(&smA[(w * 16 + g) * AROW + c0 + 8]);
                const float2 v3 = *reinterpret_cast<const float2*>(&smA[(w * 16 + g + 8) * AROW + c0 + 8]);
                uint32_t a0, a1, a2, a3;
                CVT_H2(a0, v0.y, v0.x);
                CVT_H2(a1, v1.y, v1.x);
                CVT_H2(a2, v2.y, v2.x);
                CVT_H2(a3, v3.y, v3.x);
                int kk = ks * 16;
#pragma unroll
                for (int ntp = 0; ntp < 3; ntp++) {
                    uint32_t b0, b1, b2, b3;
                    uint32_t boff = (uint32_t)(b_off + ntp * 16 * BROW + kk) * 2;
                    LDSM4(b0, b1, b2, b3, bb2 + boff);
                    MMA(acc[ntp * 2],     a0, a1, a2, a3, b0, b1);
                    MMA(acc[ntp * 2 + 1], a0, a1, a2, a3, b2, b3);
                }
            }
        }

        const int v0r = row0 + w * 16 + g;
#pragma unroll
        for (int nt = 0; nt < 6; nt++) {
            int c0 = nt * 8 + tig * 2;
#pragma unroll
            for (int half = 0; half < 2; half++) {
                int v = v0r + half * 8;
                if (v < NP) {
#pragma unroll
                    for (int e2 = 0; e2 < 2; e2++) {
                        int c = c0 + e2;
                        int bo = c / 3, e = c - bo * 3;
                        atomicAdd(out + (size_t)bo * NP * 3 + (size_t)v * 3 + e,
                                  acc[nt][half * 2 + e2]);
                    }
                }
            }
        }

        start += seg;
        remn  -= seg;
        if (remn > 0) __syncthreads();
    }
}

// ---------------------------------------------------------------------------
extern "C" void kernel_launch(void* const* d_in, const int* in_sizes, int n_in,
                              void* d_out, int out_size) {
    const float* geo   = (const float*)d_in[0];
    const int*   nb    = (const int*)d_in[1];
    const float* recon = (const float*)d_in[2];
    const float* vdiff = (const float*)d_in[3];
    float* out = (float*)d_out;

    cudaFuncSetAttribute(gemm_mma, cudaFuncAttributeMaxDynamicSharedMemorySize,
                         DSMEM);

    ftoT_kernel<<<NP / 16, 256>>>(geo, reinterpret_cast<float4*>(out));
    bvec_kernel<<<(BATCH * NP + 255) / 256, 256>>>(nb, vdiff);
    gemm_mma<<<NCTA, 256, DSMEM>>>(recon, out);
}

// round 9
// speedup vs baseline: 1.0332x; 1.0332x over previous
#include <cuda_runtime.h>
#include <cuda_fp16.h>
#include <math.h>
#include <stdint.h>

#define BATCH 16
#define NP    10000
#define NNB   10
#define NCOL  48
#define BPAD  10016          // padded K for B operand (multiple of 32)
#define BK    32
#define NKT   313            // ceil(10000/32)
#define MT    128
#define NMT   79             // ceil(10000/128)
#define TILES_TOTAL (NMT * NKT)   // 24727
#define NCTA  444            // 148 SMs x 3 CTAs
#define WBASE (TILES_TOTAL / NCTA)        // 55
#define WREM  (TILES_TOTAL - WBASE * NCTA) // 307

// GEMM smem geometry (bytes)
#define AROW  40                       // A row stride in fp32 elems (160 B)
#define BROW  40                       // B row stride in fp16 elems (80 B)
#define A_BYTES (128 * AROW * 4)       // 20480
#define B_BYTES (NCOL * BROW * 2)      // 3840
#define STAGE_BYTES (A_BYTES + B_BYTES)  // 24320
#define NSTAGE 3
#define DSMEM (NSTAGE * STAGE_BYTES)   // 72960

// ---------------- scratch (__device__ globals; zero-init) ------------------
__device__ __align__(16) float g_T[NP * BATCH * 9];   // [p][b][9]
__device__ __align__(16) __half g_bh[NCOL * BPAD];    // B fp16 [c][k]

__device__ __forceinline__ uint32_t smem_u32(const void* p) {
    uint32_t a;
    asm("{ .reg .u64 t; cvta.to.shared.u64 t, %1; cvt.u32.u64 %0, t; }"
        : "=r"(a) : "l"(p));
    return a;
}

#define LDSM4(r0, r1, r2, r3, addr) \
    asm volatile("ldmatrix.sync.aligned.m8n8.x4.shared.b16 {%0,%1,%2,%3}, [%4];" \
                 : "=r"(r0), "=r"(r1), "=r"(r2), "=r"(r3) : "r"(addr))

#define MMA(d, a0, a1, a2, a3, b0, b1) \
    asm volatile("mma.sync.aligned.m16n8k16.row.col.f32.f16.f16.f32 " \
                 "{%0,%1,%2,%3}, {%4,%5,%6,%7}, {%8,%9}, {%0,%1,%2,%3};" \
                 : "+f"((d)[0]), "+f"((d)[1]), "+f"((d)[2]), "+f"((d)[3]) \
                 : "r"(a0), "r"(a1), "r"(a2), "r"(a3), "r"(b0), "r"(b1))

#define CVT_H2(d, hi, lo) \
    asm("cvt.rn.f16x2.f32 %0, %1, %2;" : "=r"(d) : "f"(hi), "f"(lo))

#define CPA16(dst, src, sz) \
    asm volatile("cp.async.cg.shared.global [%0], [%1], 16, %2;" \
                 :: "r"(dst), "l"(src), "r"(sz) : "memory")
#define CPA_COMMIT() asm volatile("cp.async.commit_group;" ::: "memory")

// ---------------------------------------------------------------------------
// Kernel 1 (R7 version): T[b,p] = R @ S; store [p][b][9]. Zeroes output.
// ---------------------------------------------------------------------------
__global__ __launch_bounds__(256) void ftoT_kernel(const float* __restrict__ geo,
                                                   float4* __restrict__ outz) {
    __shared__ float sT[16 * 145];

    const int tid = threadIdx.x;
    const int bb = tid >> 4;
    const int pi = tid & 15;
    const int p0 = blockIdx.x * 16;
    const int p  = p0 + pi;

    {
        int g = blockIdx.x * 256 + tid;
        if (g < 120000)
            outz[g] = make_float4(0.f, 0.f, 0.f, 0.f);
    }

    const float* f = geo + (size_t)(bb * NP + p) * 9;
    float x = f[0], y = f[1], z = f[2];
    float s3 = f[3], s4 = f[4], s5 = f[5], s6 = f[6], s7 = f[7], s8 = f[8];

    float th = sqrtf(x * x + y * y + z * z);
    float R00, R01, R02, R10, R11, R12, R20, R21, R22;
    if (th == 0.0f) {
        R00 = 1.f; R01 = 0.f; R02 = 0.f;
        R10 = 0.f; R11 = 1.f; R12 = 0.f;
        R20 = 0.f; R21 = 0.f; R22 = 1.f;
    } else {
        float inv = 1.0f / th;
        float ka = x * inv, kb = y * inv, kc = z * inv;
        float st, ct;
        __sincosf(th, &st, &ct);
        float omc = 1.0f - ct;
        R00 = 1.0f - omc * (ka * ka + kb * kb);
        R01 =  st * ka - omc * kb * kc;
        R02 =  st * kb + omc * ka * kc;
        R10 = -st * ka - omc * kb * kc;
        R11 = 1.0f - omc * (ka * ka + kc * kc);
        R12 =  st * kc - omc * ka * kb;
        R20 = -st * kb + omc * ka * kc;
        R21 = -st * kc - omc * ka * kb;
        R22 = 1.0f - omc * (kb * kb + kc * kc);
    }
    float* o = sT + pi * 145 + bb * 9;
    o[0] = R00 * s3 + R01 * s4 + R02 * s5;
    o[1] = R00 * s4 + R01 * s6 + R02 * s7;
    o[2] = R00 * s5 + R01 * s7 + R02 * s8;
    o[3] = R10 * s3 + R11 * s4 + R12 * s5;
    o[4] = R10 * s4 + R11 * s6 + R12 * s7;
    o[5] = R10 * s5 + R11 * s7 + R12 * s8;
    o[6] = R20 * s3 + R21 * s4 + R22 * s5;
    o[7] = R20 * s4 + R21 * s6 + R22 * s7;
    o[8] = R20 * s5 + R21 * s7 + R22 * s8;
    __syncthreads();

    float4* dst = reinterpret_cast<float4*>(g_T + (size_t)p0 * 144);
#pragma unroll
    for (int q = tid; q < 576; q += 256) {
        int prow = q / 36;
        int s = q - prow * 36;
        const float* sp = sT + prow * 145 + s * 4;
        dst[q] = make_float4(sp[0], sp[1], sp[2], sp[3]);
    }
}

// ---------------------------------------------------------------------------
// Kernel 2: bvec with smem-staged nb/vdiff (removes 16x redundant loads).
// Block = 16 p x 16 b.  T gathers: dense [p][b][9] scalar (R7 layout).
// ---------------------------------------------------------------------------
__global__ __launch_bounds__(256) void bvec_kernel(const int* __restrict__ nb,
                                                   const float* __restrict__ vdiff) {
    __shared__ int   s_nb[160];    // 16 p x 10
    __shared__ float s_vd[480];    // 16 p x 30

    const int tid = threadIdx.x;
    const int bb = tid & 15;
    const int pi = tid >> 4;
    const int p0 = blockIdx.x * 16;
    const int p  = p0 + pi;

    if (tid < 160) s_nb[tid] = __ldg(nb + p0 * NNB + tid);
    if (tid < 120) {
        float4 v = __ldg(reinterpret_cast<const float4*>(vdiff + (size_t)p0 * 30) + tid);
        *reinterpret_cast<float4*>(&s_vd[tid * 4]) = v;
    }
    __syncthreads();

    const float* Tp = g_T + ((size_t)p * BATCH + bb) * 9;
    float T0 = Tp[0], T1 = Tp[1], T2 = Tp[2];
    float T3 = Tp[3], T4 = Tp[4], T5 = Tp[5];
    float T6 = Tp[6], T7 = Tp[7], T8 = Tp[8];

    float a0 = 0.f, a1 = 0.f, a2 = 0.f;
    float v0s = 0.f, v1s = 0.f, v2s = 0.f;

#pragma unroll
    for (int n = 0; n < NNB; n++) {
        int idx = s_nb[pi * NNB + n];
        float v0 = s_vd[pi * 30 + n * 3 + 0];
        float v1 = s_vd[pi * 30 + n * 3 + 1];
        float v2 = s_vd[pi * 30 + n * 3 + 2];
        v0s += v0; v1s += v1; v2s += v2;
        if (idx > 0) {
            const float* Tn = g_T + ((size_t)(idx - 1) * BATCH + bb) * 9;
            a0 += Tn[0] * v0 + Tn[1] * v1 + Tn[2] * v2;
            a1 += Tn[3] * v0 + Tn[4] * v1 + Tn[5] * v2;
            a2 += Tn[6] * v0 + Tn[7] * v1 + Tn[8] * v2;
        }
    }
    a0 += T0 * v0s + T1 * v1s + T2 * v2s;
    a1 += T3 * v0s + T4 * v1s + T5 * v2s;
    a2 += T6 * v0s + T7 * v1s + T8 * v2s;

    int c = bb * 3;
    g_bh[(size_t)(c + 0) * BPAD + p] = __float2half_rn(a0);
    g_bh[(size_t)(c + 1) * BPAD + p] = __float2half_rn(a1);
    g_bh[(size_t)(c + 2) * BPAD + p] = __float2half_rn(a2);
}

// ---------------------------------------------------------------------------
// Kernel 3: stream-K fp16 GEMM (R7 version, unchanged).
// ---------------------------------------------------------------------------
__global__ __launch_bounds__(256, 3) void gemm_mma(const float* __restrict__ A,
                                                   float* __restrict__ out) {
    extern __shared__ __align__(16) char dsm[];

    const int t = threadIdx.x;
    const int w = t >> 5;
    const int l = t & 31;

    const int g   = l >> 2;
    const int tig = l & 3;
    const int mat = l >> 3, mrow = l & 7;

    const uint32_t smb = smem_u32(dsm);
    const int b_off = (((mat >> 1) << 3) + mrow) * BROW + ((mat & 1) << 3);

    const bool bldr = (t < 192);
    const int br = t >> 2, bseg = t & 3;

    const int ct = blockIdx.x;
    int start = ct * WBASE + (ct < WREM ? ct : WREM);
    int remn  = WBASE + (ct < WREM ? 1 : 0);

    while (remn > 0) {
        const int m   = start / NKT;
        const int kti = start - m * NKT;
        int seg = NKT - kti; if (seg > remn) seg = remn;
        const int row0 = m * MT;

        float acc[6][4];
#pragma unroll
        for (int i = 0; i < 6; i++)
#pragma unroll
            for (int j = 0; j < 4; j++) acc[i][j] = 0.f;

        auto issue_tile = [&](int i) {
            int k0 = (kti + i) * BK;
            int st = i % NSTAGE;
            uint32_t abase = smb + st * STAGE_BYTES;
            uint32_t bbase = abase + A_BYTES;
#pragma unroll
            for (int j = 0; j < 4; j++) {
                int q = j * 256 + t;
                int r = q >> 3, c = q & 7;
                int grow = row0 + r, gk = k0 + c * 4;
                uint32_t sz = (grow < NP && gk < NP) ? 16u : 0u;
                CPA16(abase + (uint32_t)(r * AROW + c * 4) * 4,
                      A + (size_t)grow * NP + gk, sz);
            }
            if (bldr) {
                CPA16(bbase + (uint32_t)(br * BROW + bseg * 8) * 2,
                      g_bh + (size_t)br * BPAD + k0 + bseg * 8, 16u);
            }
            CPA_COMMIT();
        };

        issue_tile(0);
        if (seg > 1) issue_tile(1);
        else CPA_COMMIT();

        for (int i = 0; i < seg; i++) {
            if (i + 1 < seg) {
                asm volatile("cp.async.wait_group 1;" ::: "memory");
            } else {
                asm volatile("cp.async.wait_group 0;" ::: "memory");
            }
            __syncthreads();
            if (i + 2 < seg) issue_tile(i + 2);

            int st = i % NSTAGE;
            const float* smA = reinterpret_cast<const float*>(dsm + st * STAGE_BYTES);
            uint32_t bb2 = smb + st * STAGE_BYTES + A_BYTES;

#pragma unroll
            for (int ks = 0; ks < 2; ks++) {
                const int c0 = ks * 16 + tig * 2;
                const float2 v0 = *reinterpret_cast<const float2*>(&smA[(w * 16 + g) * AROW + c0]);
                const float2 v1 = *reinterpret_cast<const float2*>(&smA[(w * 16 + g + 8) * AROW + c0]);
                const float2 v2 = *reinterpret_cast<const float2*>(&smA[(w * 16 + g) * AROW + c0 + 8]);
                const float2 v3 = *reinterpret_cast<const float2*>(&smA[(w * 16 + g + 8) * AROW + c0 + 8]);
                uint32_t a0, a1, a2, a3;
                CVT_H2(a0, v0.y, v0.x);
                CVT_H2(a1, v1.y, v1.x);
                CVT_H2(a2, v2.y, v2.x);
                CVT_H2(a3, v3.y, v3.x);
                int kk = ks * 16;
#pragma unroll
                for (int ntp = 0; ntp < 3; ntp++) {
                    uint32_t b0, b1, b2, b3;
                    uint32_t boff = (uint32_t)(b_off + ntp * 16 * BROW + kk) * 2;
                    LDSM4(b0, b1, b2, b3, bb2 + boff);
                    MMA(acc[ntp * 2],     a0, a1, a2, a3, b0, b1);
                    MMA(acc[ntp * 2 + 1], a0, a1, a2, a3, b2, b3);
                }
            }
        }

        const int v0r = row0 + w * 16 + g;
#pragma unroll
        for (int nt = 0; nt < 6; nt++) {
            int c0 = nt * 8 + tig * 2;
#pragma unroll
            for (int half = 0; half < 2; half++) {
                int v = v0r + half * 8;
                if (v < NP) {
#pragma unroll
                    for (int e2 = 0; e2 < 2; e2++) {
                        int c = c0 + e2;
                        int bo = c / 3, e = c - bo * 3;
                        atomicAdd(out + (size_t)bo * NP * 3 + (size_t)v * 3 + e,
                                  acc[nt][half * 2 + e2]);
                    }
                }
            }
        }

        start += seg;
        remn  -= seg;
        if (remn > 0) __syncthreads();
    }
}

// ---------------------------------------------------------------------------
extern "C" void kernel_launch(void* const* d_in, const int* in_sizes, int n_in,
                              void* d_out, int out_size) {
    const float* geo   = (const float*)d_in[0];
    const int*   nb    = (const int*)d_in[1];
    const float* recon = (const float*)d_in[2];
    const float* vdiff = (const float*)d_in[3];
    float* out = (float*)d_out;

    cudaFuncSetAttribute(gemm_mma, cudaFuncAttributeMaxDynamicSharedMemorySize,
                         DSMEM);

    ftoT_kernel<<<NP / 16, 256>>>(geo, reinterpret_cast<float4*>(out));
    bvec_kernel<<<NP / 16, 256>>>(nb, vdiff);
    gemm_mma<<<NCTA, 256, DSMEM>>>(recon, out);
}